// round 3
// baseline (speedup 1.0000x reference)
#include <cuda_runtime.h>
#include <cstdint>

#define B_  32
#define S_  512
#define H_  1024
#define V_  250002

#define TOK (B_ * S_)          // 16384
#define OFF_DENSE  0
#define OFF_SPARSE (B_ * H_)                 // 32768
#define OFF_MV     (OFF_SPARSE + B_ * V_)    // 8032832

#define EPS 1e-12f

// Scratch (allocation-free rule: __device__ globals)
__device__ float g_pooled[B_ * H_];   // raw masked sum over S
__device__ float g_masksum[B_];

// ---------------------------------------------------------------------------
// Zero the sparse output region (d_out is poisoned with 0xAA).
// ---------------------------------------------------------------------------
__global__ void zero_sparse_kernel(float* __restrict__ sparse) {
    const int n4 = (B_ * V_) / 4;  // 8000064 / 4 = 2000016
    float4 z = make_float4(0.f, 0.f, 0.f, 0.f);
    float4* p = reinterpret_cast<float4*>(sparse);
    for (int i = blockIdx.x * blockDim.x + threadIdx.x; i < n4;
         i += gridDim.x * blockDim.x)
        p[i] = z;
    // B_*V_ = 8000064 is divisible by 4, no tail.
}

// ---------------------------------------------------------------------------
// Masked mean-pool accumulation: pooled[b,h] = sum_s x[b,s,h]*mask[b,s]
// grid: (B_, H_/128). block: 128. Also computes masksum[b] (chunk 0 blocks).
// ---------------------------------------------------------------------------
__global__ void pool_kernel(const float* __restrict__ x,
                            const float* __restrict__ mask) {
    const int b = blockIdx.x;
    const int h = blockIdx.y * 128 + threadIdx.x;

    __shared__ float msk[S_];
    for (int i = threadIdx.x; i < S_; i += 128) msk[i] = mask[b * S_ + i];
    __syncthreads();

    const float* xp = x + (size_t)b * S_ * H_ + h;
    float acc = 0.f;
#pragma unroll 8
    for (int s = 0; s < S_; s++) acc += xp[(size_t)s * H_] * msk[s];
    g_pooled[b * H_ + h] = acc;

    if (blockIdx.y == 0) {
        // reduce masksum
        float p = msk[threadIdx.x] + msk[threadIdx.x + 128] +
                  msk[threadIdx.x + 256] + msk[threadIdx.x + 384];
#pragma unroll
        for (int o = 16; o > 0; o >>= 1)
            p += __shfl_down_sync(0xffffffffu, p, o);
        __shared__ float warp_s[4];
        if ((threadIdx.x & 31) == 0) warp_s[threadIdx.x >> 5] = p;
        __syncthreads();
        if (threadIdx.x == 0)
            g_masksum[b] = warp_s[0] + warp_s[1] + warp_s[2] + warp_s[3];
    }
}

// ---------------------------------------------------------------------------
// Sparse head: per-token dot with sparse_w, relu, scatter-add into [B,V].
// grid: TOK blocks of 128 threads. ids are int32 (JAX downcasts int64).
// ---------------------------------------------------------------------------
__global__ void sparse_kernel(const float* __restrict__ x,
                              const float* __restrict__ mask,
                              const float* __restrict__ sw,
                              const float* __restrict__ sb,
                              const int* __restrict__ ids,
                              float* __restrict__ sparse) {
    const int t = blockIdx.x;           // token index
    const float* xp = x + (size_t)t * H_;
    float acc = 0.f;
#pragma unroll
    for (int i = 0; i < H_ / 128; i++) {
        int k = i * 128 + threadIdx.x;
        acc += xp[k] * sw[k];
    }
#pragma unroll
    for (int o = 16; o > 0; o >>= 1)
        acc += __shfl_down_sync(0xffffffffu, acc, o);
    __shared__ float warp_s[4];
    if ((threadIdx.x & 31) == 0) warp_s[threadIdx.x >> 5] = acc;
    __syncthreads();
    if (threadIdx.x == 0) {
        float dot = warp_s[0] + warp_s[1] + warp_s[2] + warp_s[3];
        float tw = (dot + sb[0]) * mask[t];
        tw = tw > 0.f ? tw : 0.f;
        int b = t / S_;
        int id = ids[t];
        if (id >= 0 && id < V_)
            atomicAdd(sparse + (size_t)b * V_ + id, tw);
    }
}

// ---------------------------------------------------------------------------
// Dense head GEMM: out[b,h] = tanh( (pooled[b,:]/msum[b]) . dense_w[h,:] + bias[h] )
// grid: (H_/128, B_). block: 128 (one thread per h).
// ---------------------------------------------------------------------------
__global__ void dense_kernel(const float* __restrict__ dw,
                             const float* __restrict__ db,
                             float* __restrict__ out) {
    const int b = blockIdx.y;
    const int h = blockIdx.x * 128 + threadIdx.x;

    __shared__ float ps[H_];
    for (int i = threadIdx.x; i < H_; i += 128) ps[i] = g_pooled[b * H_ + i];
    __syncthreads();

    const float pinv = 1.f / g_masksum[b];
    const float* wr = dw + (size_t)h * H_;
    float acc = 0.f;
#pragma unroll 8
    for (int k = 0; k < H_; k++) acc += ps[k] * wr[k];
    out[b * H_ + h] = tanhf(acc * pinv + db[h]);
}

// ---------------------------------------------------------------------------
// Generic row L2-normalize in place: rows of length H_=1024.
// block: 256 threads (1 float4 each). grid: nrows.
// ---------------------------------------------------------------------------
__global__ void l2norm_kernel(float* __restrict__ data) {
    float4* row = reinterpret_cast<float4*>(data + (size_t)blockIdx.x * H_);
    float4 v = row[threadIdx.x];
    float ss = v.x * v.x + v.y * v.y + v.z * v.z + v.w * v.w;
#pragma unroll
    for (int o = 16; o > 0; o >>= 1)
        ss += __shfl_down_sync(0xffffffffu, ss, o);
    __shared__ float warp_s[8];
    if ((threadIdx.x & 31) == 0) warp_s[threadIdx.x >> 5] = ss;
    __syncthreads();
    if (threadIdx.x < 8) {
        float t = warp_s[threadIdx.x];
#pragma unroll
        for (int o = 4; o > 0; o >>= 1)
            t += __shfl_down_sync(0xffu, t, o);
        if (threadIdx.x == 0) warp_s[0] = t;
    }
    __syncthreads();
    float norm = sqrtf(warp_s[0]);
    float scale = 1.f / fmaxf(norm, EPS);
    v.x *= scale; v.y *= scale; v.z *= scale; v.w *= scale;
    row[threadIdx.x] = v;
}

// ---------------------------------------------------------------------------
// MV GEMM: C[t,n] = ( A[t,:] . W[n,:] + bias[n] ) * mask[t]
// A = hidden [16384,1024], W = mv_w [1024,1024], both row-major (K contiguous).
// Tiles: BM=128, BN=64, BK=16; 256 threads; 8x4 per-thread micro-tile.
// ---------------------------------------------------------------------------
#define BM 128
#define BN 64
#define BK 16
#define APAD 4
#define BPAD 4
#define LDA_S (BM + APAD)   // 132
#define LDB_S (BN + BPAD)   // 68

__global__ __launch_bounds__(256, 2)
void mv_gemm_kernel(const float* __restrict__ A,
                    const float* __restrict__ W,
                    const float* __restrict__ bias,
                    const float* __restrict__ mask,
                    float* __restrict__ C) {
    __shared__ float As[BK * LDA_S];
    __shared__ float Ws[BK * LDB_S];

    const int m0 = blockIdx.y * BM;
    const int n0 = blockIdx.x * BN;
    const int tid = threadIdx.x;

    const int tm = tid >> 4;       // 0..15 -> m micro-row group (8 rows)
    const int tn = tid & 15;       // 0..15 -> n micro-col group (4 cols)

    float acc[8][4];
#pragma unroll
    for (int i = 0; i < 8; i++)
#pragma unroll
        for (int j = 0; j < 4; j++) acc[i][j] = 0.f;

    const int wr  = tid >> 2;         // 0..63
    const int wc4 = tid & 3;

    for (int kt = 0; kt < H_; kt += BK) {
        // --- load A tile [BM x BK] transposed into As[k][m] ---
#pragma unroll
        for (int i = 0; i < 2; i++) {
            int e = tid + i * 256;
            int r = e >> 2, c4 = e & 3;
            float4 v = *reinterpret_cast<const float4*>(
                A + (size_t)(m0 + r) * H_ + kt + c4 * 4);
            As[(c4 * 4 + 0) * LDA_S + r] = v.x;
            As[(c4 * 4 + 1) * LDA_S + r] = v.y;
            As[(c4 * 4 + 2) * LDA_S + r] = v.z;
            As[(c4 * 4 + 3) * LDA_S + r] = v.w;
        }
        // --- load W tile [BN x BK] transposed into Ws[k][n] ---
        {
            float4 v = *reinterpret_cast<const float4*>(
                W + (size_t)(n0 + wr) * H_ + kt + wc4 * 4);
            Ws[(wc4 * 4 + 0) * LDB_S + wr] = v.x;
            Ws[(wc4 * 4 + 1) * LDB_S + wr] = v.y;
            Ws[(wc4 * 4 + 2) * LDB_S + wr] = v.z;
            Ws[(wc4 * 4 + 3) * LDB_S + wr] = v.w;
        }
        __syncthreads();

#pragma unroll
        for (int k = 0; k < BK; k++) {
            float4 a0 = *reinterpret_cast<const float4*>(&As[k * LDA_S + tm * 8]);
            float4 a1 = *reinterpret_cast<const float4*>(&As[k * LDA_S + tm * 8 + 4]);
            float4 bv = *reinterpret_cast<const float4*>(&Ws[k * LDB_S + tn * 4]);
            float af[8] = {a0.x, a0.y, a0.z, a0.w, a1.x, a1.y, a1.z, a1.w};
            float bf[4] = {bv.x, bv.y, bv.z, bv.w};
#pragma unroll
            for (int i = 0; i < 8; i++)
#pragma unroll
                for (int j = 0; j < 4; j++) acc[i][j] += af[i] * bf[j];
        }
        __syncthreads();
    }

    // epilogue: + bias, * mask[token], store
    float4 b4 = *reinterpret_cast<const float4*>(bias + n0 + tn * 4);
    float bf[4] = {b4.x, b4.y, b4.z, b4.w};
#pragma unroll
    for (int i = 0; i < 8; i++) {
        int t = m0 + tm * 8 + i;
        float mk = mask[t];
        float4 o;
        o.x = (acc[i][0] + bf[0]) * mk;
        o.y = (acc[i][1] + bf[1]) * mk;
        o.z = (acc[i][2] + bf[2]) * mk;
        o.w = (acc[i][3] + bf[3]) * mk;
        *reinterpret_cast<float4*>(C + (size_t)t * H_ + n0 + tn * 4) = o;
    }
}

// ---------------------------------------------------------------------------
extern "C" void kernel_launch(void* const* d_in, const int* in_sizes, int n_in,
                              void* d_out, int out_size) {
    const float* hidden   = (const float*)d_in[0];   // [B,S,H]
    const int*   ids      = (const int*)d_in[1];     // [B,S] int32 (JAX downcast)
    const float* attn     = (const float*)d_in[2];   // [B,S]
    const float* dense_w  = (const float*)d_in[3];   // [H,H]
    const float* dense_b  = (const float*)d_in[4];   // [H]
    const float* sparse_w = (const float*)d_in[5];   // [1,H]
    const float* sparse_b = (const float*)d_in[6];   // [1]
    const float* mv_w     = (const float*)d_in[7];   // [H,H]
    const float* mv_b     = (const float*)d_in[8];   // [H]

    float* out        = (float*)d_out;
    float* out_dense  = out + OFF_DENSE;
    float* out_sparse = out + OFF_SPARSE;
    float* out_mv     = out + OFF_MV;

    // 1. zero the sparse region
    zero_sparse_kernel<<<2048, 256>>>(out_sparse);

    // 2. masked pooling (+ masksum)
    {
        dim3 g(B_, H_ / 128);
        pool_kernel<<<g, 128>>>(hidden, attn);
    }

    // 3. sparse head: token weights + scatter
    sparse_kernel<<<TOK, 128>>>(hidden, attn, sparse_w, sparse_b, ids, out_sparse);

    // 4. dense head GEMM + tanh (pre-norm)
    {
        dim3 g(H_ / 128, B_);
        dense_kernel<<<g, 128>>>(dense_w, dense_b, out_dense);
    }
    // 5. dense L2 norm (32 rows)
    l2norm_kernel<<<B_, 256>>>(out_dense);

    // 6. MV GEMM (+bias, *mask) into out_mv
    {
        dim3 g(H_ / BN, TOK / BM);   // (16, 128)
        mv_gemm_kernel<<<g, 256>>>(hidden, mv_w, mv_b, attn, out_mv);
    }
    // 7. MV per-token L2 norm (16384 rows)
    l2norm_kernel<<<TOK, 256>>>(out_mv);
}

// round 5
// speedup vs baseline: 2.3489x; 2.3489x over previous
#include <cuda_runtime.h>
#include <cuda_bf16.h>
#include <cstdint>

#define B_  32
#define S_  512
#define H_  1024
#define V_  250002

#define TOK (B_ * S_)          // 16384
#define OFF_DENSE  0
#define OFF_SPARSE (B_ * H_)                 // 32768
#define OFF_MV     (OFF_SPARSE + B_ * V_)    // 8032832

#define EPS 1e-12f

// ---------------------------------------------------------------------------
// Device-global scratch (allocation-free rule)
// ---------------------------------------------------------------------------
__device__ float g_pooled[B_ * H_];
__device__ float g_masksum[B_];
__device__ __align__(16) __nv_bfloat16 g_Ahi[TOK * H_];   // hidden hi
__device__ __align__(16) __nv_bfloat16 g_Alo[TOK * H_];   // hidden lo
__device__ __align__(16) __nv_bfloat16 g_Whi[H_ * H_];    // mv_w hi
__device__ __align__(16) __nv_bfloat16 g_Wlo[H_ * H_];    // mv_w lo

// ---------------------------------------------------------------------------
// PTX helpers (sm_80-level: cp.async, ldmatrix, mma.sync)
// ---------------------------------------------------------------------------
__device__ __forceinline__ uint32_t smem_u32(const void* p) {
    uint32_t a;
    asm("{ .reg .u64 t; cvta.to.shared.u64 t, %1; cvt.u32.u64 %0, t; }"
        : "=r"(a) : "l"(p));
    return a;
}
#define CP16(dst, src) \
    asm volatile("cp.async.cg.shared.global [%0], [%1], 16;" \
                 :: "r"(dst), "l"(src) : "memory")
#define CP_COMMIT() asm volatile("cp.async.commit_group;" ::: "memory")
#define CP_WAIT1()  asm volatile("cp.async.wait_group 1;" ::: "memory")
#define CP_WAIT0()  asm volatile("cp.async.wait_group 0;" ::: "memory")
#define LDSM_X4(r0, r1, r2, r3, addr) \
    asm volatile("ldmatrix.sync.aligned.m8n8.x4.shared.b16 {%0,%1,%2,%3}, [%4];" \
                 : "=r"(r0), "=r"(r1), "=r"(r2), "=r"(r3) : "r"(addr))
#define MMA16816(d, a, b) \
    asm volatile("mma.sync.aligned.m16n8k16.row.col.f32.bf16.bf16.f32 " \
                 "{%0,%1,%2,%3}, {%4,%5,%6,%7}, {%8,%9}, {%0,%1,%2,%3};" \
                 : "+f"((d)[0]), "+f"((d)[1]), "+f"((d)[2]), "+f"((d)[3]) \
                 : "r"((a)[0]), "r"((a)[1]), "r"((a)[2]), "r"((a)[3]), \
                   "r"((b)[0]), "r"((b)[1]))

// ---------------------------------------------------------------------------
// Zero the sparse output region
// ---------------------------------------------------------------------------
__global__ void zero_sparse_kernel(float* __restrict__ sparse) {
    const int n4 = (B_ * V_) / 4;
    float4 z = make_float4(0.f, 0.f, 0.f, 0.f);
    float4* p = reinterpret_cast<float4*>(sparse);
    for (int i = blockIdx.x * blockDim.x + threadIdx.x; i < n4;
         i += gridDim.x * blockDim.x)
        p[i] = z;
}

// ---------------------------------------------------------------------------
// Split fp32 -> bf16 hi/lo
// ---------------------------------------------------------------------------
__global__ void split_bf16_kernel(const float4* __restrict__ src,
                                  __nv_bfloat162* __restrict__ hi,
                                  __nv_bfloat162* __restrict__ lo, int n4) {
    for (int i = blockIdx.x * blockDim.x + threadIdx.x; i < n4;
         i += gridDim.x * blockDim.x) {
        float4 v = src[i];
        __nv_bfloat162 h01 = __floats2bfloat162_rn(v.x, v.y);
        __nv_bfloat162 h23 = __floats2bfloat162_rn(v.z, v.w);
        float2 f01 = __bfloat1622float2(h01);
        float2 f23 = __bfloat1622float2(h23);
        __nv_bfloat162 l01 = __floats2bfloat162_rn(v.x - f01.x, v.y - f01.y);
        __nv_bfloat162 l23 = __floats2bfloat162_rn(v.z - f23.x, v.w - f23.y);
        hi[i * 2 + 0] = h01;  hi[i * 2 + 1] = h23;
        lo[i * 2 + 0] = l01;  lo[i * 2 + 1] = l23;
    }
}

// ---------------------------------------------------------------------------
// Masked mean-pool accumulation
// ---------------------------------------------------------------------------
__global__ void pool_kernel(const float* __restrict__ x,
                            const float* __restrict__ mask) {
    const int b = blockIdx.x;
    const int h = blockIdx.y * 128 + threadIdx.x;

    __shared__ float msk[S_];
    for (int i = threadIdx.x; i < S_; i += 128) msk[i] = mask[b * S_ + i];
    __syncthreads();

    const float* xp = x + (size_t)b * S_ * H_ + h;
    float acc = 0.f;
#pragma unroll 8
    for (int s = 0; s < S_; s++) acc += xp[(size_t)s * H_] * msk[s];
    g_pooled[b * H_ + h] = acc;

    if (blockIdx.y == 0) {
        float p = msk[threadIdx.x] + msk[threadIdx.x + 128] +
                  msk[threadIdx.x + 256] + msk[threadIdx.x + 384];
#pragma unroll
        for (int o = 16; o > 0; o >>= 1)
            p += __shfl_down_sync(0xffffffffu, p, o);
        __shared__ float warp_s[4];
        if ((threadIdx.x & 31) == 0) warp_s[threadIdx.x >> 5] = p;
        __syncthreads();
        if (threadIdx.x == 0)
            g_masksum[b] = warp_s[0] + warp_s[1] + warp_s[2] + warp_s[3];
    }
}

// ---------------------------------------------------------------------------
// Sparse head
// ---------------------------------------------------------------------------
__global__ void sparse_kernel(const float* __restrict__ x,
                              const float* __restrict__ mask,
                              const float* __restrict__ sw,
                              const float* __restrict__ sb,
                              const int* __restrict__ ids,
                              float* __restrict__ sparse) {
    const int t = blockIdx.x;
    const float* xp = x + (size_t)t * H_;
    float acc = 0.f;
#pragma unroll
    for (int i = 0; i < H_ / 128; i++) {
        int k = i * 128 + threadIdx.x;
        acc += xp[k] * sw[k];
    }
#pragma unroll
    for (int o = 16; o > 0; o >>= 1)
        acc += __shfl_down_sync(0xffffffffu, acc, o);
    __shared__ float warp_s[4];
    if ((threadIdx.x & 31) == 0) warp_s[threadIdx.x >> 5] = acc;
    __syncthreads();
    if (threadIdx.x == 0) {
        float dot = warp_s[0] + warp_s[1] + warp_s[2] + warp_s[3];
        float tw = (dot + sb[0]) * mask[t];
        tw = tw > 0.f ? tw : 0.f;
        int b = t / S_;
        int id = ids[t];
        if (id >= 0 && id < V_)
            atomicAdd(sparse + (size_t)b * V_ + id, tw);
    }
}

// ---------------------------------------------------------------------------
// Dense head: block = 8 h-rows x 32 b; weights staged through padded SMEM.
// ---------------------------------------------------------------------------
__global__ __launch_bounds__(256, 4)
void dense_kernel2(const float* __restrict__ dw,
                   const float* __restrict__ db,
                   float* __restrict__ out) {
    __shared__ float ws[8][H_ + 1];
    const int tid = threadIdx.x;
    const int h0 = blockIdx.x * 8;
#pragma unroll
    for (int i = 0; i < 32; i++) {
        int idx = tid + i * 256;
        int r = idx >> 10, c = idx & 1023;
        ws[r][c] = dw[(size_t)(h0 + r) * H_ + c];
    }
    __syncthreads();
    const int b = tid >> 3;
    const int hi = tid & 7;
    const float* p = g_pooled + b * H_;
    float acc = 0.f;
#pragma unroll 8
    for (int k = 0; k < H_; k++) acc += p[k] * ws[hi][k];
    const float pinv = 1.f / g_masksum[b];
    out[b * H_ + h0 + hi] = tanhf(acc * pinv + db[h0 + hi]);
}

// ---------------------------------------------------------------------------
// Row L2-normalize in place (rows of H_=1024)
// ---------------------------------------------------------------------------
__global__ void l2norm_kernel(float* __restrict__ data) {
    float4* row = reinterpret_cast<float4*>(data + (size_t)blockIdx.x * H_);
    float4 v = row[threadIdx.x];
    float ss = v.x * v.x + v.y * v.y + v.z * v.z + v.w * v.w;
#pragma unroll
    for (int o = 16; o > 0; o >>= 1)
        ss += __shfl_down_sync(0xffffffffu, ss, o);
    __shared__ float warp_s[8];
    if ((threadIdx.x & 31) == 0) warp_s[threadIdx.x >> 5] = ss;
    __syncthreads();
    if (threadIdx.x < 8) {
        float t = warp_s[threadIdx.x];
#pragma unroll
        for (int o = 4; o > 0; o >>= 1)
            t += __shfl_down_sync(0xffu, t, o);
        if (threadIdx.x == 0) warp_s[0] = t;
    }
    __syncthreads();
    float scale = 1.f / fmaxf(sqrtf(warp_s[0]), EPS);
    v.x *= scale; v.y *= scale; v.z *= scale; v.w *= scale;
    row[threadIdx.x] = v;
}

// ---------------------------------------------------------------------------
// MV GEMM via mma.sync bf16 (split hi/lo, 3 passes), cp.async double buffer.
// CTA 128x128, BK=64. 8 warps (2x4), warp tile 64x32.
// SMEM stage (65536 B): Ahi @0, Alo @16384, Whi @32768, Wlo @49152.
// Tiles are [128 rows][64 bf16] = [128][128B], SW128-swizzled per 16B chunk.
// ---------------------------------------------------------------------------
#define NCH 16                 // 1024 / 64
#define STG 65536

__device__ __forceinline__ void stage_load(uint32_t smb, int s, int ch,
                                           int m0, int n0, int tid) {
    const int kt = ch * 64;
    const __nv_bfloat16* srcs[4] = {g_Ahi, g_Alo, g_Whi, g_Wlo};
    const int row0s[4] = {m0, m0, n0, n0};
#pragma unroll
    for (int t4 = 0; t4 < 4; t4++) {
        const __nv_bfloat16* src = srcs[t4];
        const int row0 = row0s[t4];
        const uint32_t tb = smb + s * STG + t4 * 16384;
#pragma unroll
        for (int it = 0; it < 4; it++) {
            int q = tid + it * 256;          // 0..1023
            int r = q >> 3, c16 = q & 7;
            const void* g = src + (size_t)(row0 + r) * H_ + kt + c16 * 8;
            uint32_t d = tb + (uint32_t)(r * 128 + ((c16 ^ (r & 7)) << 4));
            CP16(d, g);
        }
    }
}

__global__ __launch_bounds__(256, 1)
void mv_gemm_mma(const float* __restrict__ bias,
                 const float* __restrict__ mask,
                 float* __restrict__ C) {
    extern __shared__ char sm[];
    const uint32_t smb = smem_u32(sm);

    const int tid = threadIdx.x;
    const int wid = tid >> 5, lane = tid & 31;
    const int warp_m = wid & 1;        // 0..1 -> 64-row half
    const int warp_n = wid >> 1;       // 0..3 -> 32-col quarter
    const int m0 = blockIdx.y * 128, n0 = blockIdx.x * 128;

    float acc[4][4][4];
#pragma unroll
    for (int i = 0; i < 4; i++)
#pragma unroll
        for (int j = 0; j < 4; j++)
#pragma unroll
            for (int k = 0; k < 4; k++) acc[i][j][k] = 0.f;

    // ldmatrix lane addressing (precomputed pieces)
    const int g8 = lane >> 3, i8 = lane & 7;
    // A: row = base + (g8&1)*8 + i8 ; chunk += (g8>>1)
    const int a_r = warp_m * 64 + (g8 & 1) * 8 + i8;
    const int a_cadd = g8 >> 1;
    // B: row = base + (g8>>1)*8 + i8 ; chunk += (g8&1)
    const int b_r = warp_n * 32 + (g8 >> 1) * 8 + i8;
    const int b_cadd = g8 & 1;

    stage_load(smb, 0, 0, m0, n0, tid);
    CP_COMMIT();

    for (int ch = 0; ch < NCH; ch++) {
        const int s = ch & 1;
        if (ch + 1 < NCH) {
            stage_load(smb, s ^ 1, ch + 1, m0, n0, tid);
            CP_COMMIT();
            CP_WAIT1();
        } else {
            CP_WAIT0();
        }
        __syncthreads();

        const uint32_t ah = smb + s * STG;
        const uint32_t al = ah + 16384;
        const uint32_t wh = ah + 32768;
        const uint32_t wl = ah + 49152;

#pragma unroll
        for (int ks = 0; ks < 4; ks++) {
            uint32_t Ahi[4][4], Alo[4][4];
#pragma unroll
            for (int mt = 0; mt < 4; mt++) {
                int r = a_r + mt * 16;
                int c16 = ks * 2 + a_cadd;
                uint32_t off = (uint32_t)(r * 128 + ((c16 ^ (r & 7)) << 4));
                LDSM_X4(Ahi[mt][0], Ahi[mt][1], Ahi[mt][2], Ahi[mt][3], ah + off);
                LDSM_X4(Alo[mt][0], Alo[mt][1], Alo[mt][2], Alo[mt][3], al + off);
            }
            uint32_t Bhi[4][2], Blo[4][2];
#pragma unroll
            for (int bh = 0; bh < 2; bh++) {
                int r = b_r + bh * 16;
                int c16 = ks * 2 + b_cadd;
                uint32_t off = (uint32_t)(r * 128 + ((c16 ^ (r & 7)) << 4));
                uint32_t t0, t1, t2, t3;
                LDSM_X4(t0, t1, t2, t3, wh + off);
                Bhi[2 * bh][0] = t0; Bhi[2 * bh][1] = t1;
                Bhi[2 * bh + 1][0] = t2; Bhi[2 * bh + 1][1] = t3;
                LDSM_X4(t0, t1, t2, t3, wl + off);
                Blo[2 * bh][0] = t0; Blo[2 * bh][1] = t1;
                Blo[2 * bh + 1][0] = t2; Blo[2 * bh + 1][1] = t3;
            }
#pragma unroll
            for (int mt = 0; mt < 4; mt++)
#pragma unroll
                for (int ng = 0; ng < 4; ng++) {
                    MMA16816(acc[mt][ng], Ahi[mt], Bhi[ng]);
                    MMA16816(acc[mt][ng], Ahi[mt], Blo[ng]);
                    MMA16816(acc[mt][ng], Alo[mt], Bhi[ng]);
                }
        }
        __syncthreads();
    }

    // epilogue: + bias, * mask, store float2 pairs
#pragma unroll
    for (int mt = 0; mt < 4; mt++) {
        const int r0 = m0 + warp_m * 64 + mt * 16 + (lane >> 2);
        const float mk0 = mask[r0];
        const float mk1 = mask[r0 + 8];
#pragma unroll
        for (int ng = 0; ng < 4; ng++) {
            const int c = n0 + warp_n * 32 + ng * 8 + 2 * (lane & 3);
            const float2 b2 = *reinterpret_cast<const float2*>(bias + c);
            float2 o0, o1;
            o0.x = (acc[mt][ng][0] + b2.x) * mk0;
            o0.y = (acc[mt][ng][1] + b2.y) * mk0;
            o1.x = (acc[mt][ng][2] + b2.x) * mk1;
            o1.y = (acc[mt][ng][3] + b2.y) * mk1;
            *reinterpret_cast<float2*>(C + (size_t)r0 * H_ + c) = o0;
            *reinterpret_cast<float2*>(C + (size_t)(r0 + 8) * H_ + c) = o1;
        }
    }
}

// ---------------------------------------------------------------------------
extern "C" void kernel_launch(void* const* d_in, const int* in_sizes, int n_in,
                              void* d_out, int out_size) {
    const float* hidden   = (const float*)d_in[0];   // [B,S,H]
    const int*   ids      = (const int*)d_in[1];     // [B,S] int32
    const float* attn     = (const float*)d_in[2];   // [B,S]
    const float* dense_w  = (const float*)d_in[3];   // [H,H]
    const float* dense_b  = (const float*)d_in[4];   // [H]
    const float* sparse_w = (const float*)d_in[5];   // [1,H]
    const float* sparse_b = (const float*)d_in[6];   // [1]
    const float* mv_w     = (const float*)d_in[7];   // [H,H]
    const float* mv_b     = (const float*)d_in[8];   // [H]

    float* out        = (float*)d_out;
    float* out_dense  = out + OFF_DENSE;
    float* out_sparse = out + OFF_SPARSE;
    float* out_mv     = out + OFF_MV;

    __nv_bfloat16 *ahi, *alo, *whi, *wlo;
    cudaGetSymbolAddress((void**)&ahi, g_Ahi);
    cudaGetSymbolAddress((void**)&alo, g_Alo);
    cudaGetSymbolAddress((void**)&whi, g_Whi);
    cudaGetSymbolAddress((void**)&wlo, g_Wlo);

    // 1. zero the sparse region
    zero_sparse_kernel<<<2048, 256>>>(out_sparse);

    // 2. split hidden and mv_w into bf16 hi/lo
    split_bf16_kernel<<<8192, 256>>>((const float4*)hidden,
                                     (__nv_bfloat162*)ahi,
                                     (__nv_bfloat162*)alo, TOK * H_ / 4);
    split_bf16_kernel<<<1024, 256>>>((const float4*)mv_w,
                                     (__nv_bfloat162*)whi,
                                     (__nv_bfloat162*)wlo, H_ * H_ / 4);

    // 3. masked pooling (+ masksum)
    {
        dim3 g(B_, H_ / 128);
        pool_kernel<<<g, 128>>>(hidden, attn);
    }

    // 4. sparse head
    sparse_kernel<<<TOK, 128>>>(hidden, attn, sparse_w, sparse_b, ids, out_sparse);

    // 5. dense head + L2 norm
    dense_kernel2<<<H_ / 8, 256>>>(dense_w, dense_b, out_dense);
    l2norm_kernel<<<B_, 256>>>(out_dense);

    // 6. MV GEMM on tensor cores (mma.sync)
    {
        const int smem_bytes = 2 * STG;  // 131072
        cudaFuncSetAttribute(mv_gemm_mma,
                             cudaFuncAttributeMaxDynamicSharedMemorySize,
                             smem_bytes);
        dim3 g(H_ / 128, TOK / 128);     // (8, 128)
        mv_gemm_mma<<<g, 256, smem_bytes>>>(mv_b, attn, out_mv);
    }

    // 7. MV per-token L2 norm
    l2norm_kernel<<<TOK, 256>>>(out_mv);
}

// round 7
// speedup vs baseline: 3.0597x; 1.3026x over previous
#include <cuda_runtime.h>
#include <cuda_bf16.h>
#include <cstdint>

#define B_  32
#define S_  512
#define H_  1024
#define V_  250002

#define TOK (B_ * S_)          // 16384
#define OFF_DENSE  0
#define OFF_SPARSE (B_ * H_)                 // 32768
#define OFF_MV     (OFF_SPARSE + B_ * V_)    // 8032832

#define EPS 1e-12f

// ---------------------------------------------------------------------------
// Device-global scratch (allocation-free rule)
// ---------------------------------------------------------------------------
__device__ float g_pooled[B_ * H_];
__device__ float g_masksum[B_];
__device__ float g_tokdot[TOK];
__device__ __align__(16) __nv_bfloat16 g_Ahi[TOK * H_];
__device__ __align__(16) __nv_bfloat16 g_Alo[TOK * H_];
__device__ __align__(16) __nv_bfloat16 g_Whi[H_ * H_];
__device__ __align__(16) __nv_bfloat16 g_Wlo[H_ * H_];

// ---------------------------------------------------------------------------
// PTX helpers
// ---------------------------------------------------------------------------
__device__ __forceinline__ uint32_t smem_u32(const void* p) {
    uint32_t a;
    asm("{ .reg .u64 t; cvta.to.shared.u64 t, %1; cvt.u32.u64 %0, t; }"
        : "=r"(a) : "l"(p));
    return a;
}
#define CP16(dst, src) \
    asm volatile("cp.async.cg.shared.global [%0], [%1], 16;" \
                 :: "r"(dst), "l"(src) : "memory")
#define CP_COMMIT() asm volatile("cp.async.commit_group;" ::: "memory")
#define CP_WAIT2()  asm volatile("cp.async.wait_group 2;" ::: "memory")
#define CP_WAIT1()  asm volatile("cp.async.wait_group 1;" ::: "memory")
#define CP_WAIT0()  asm volatile("cp.async.wait_group 0;" ::: "memory")
#define LDSM_X4(r0, r1, r2, r3, addr) \
    asm volatile("ldmatrix.sync.aligned.m8n8.x4.shared.b16 {%0,%1,%2,%3}, [%4];" \
                 : "=r"(r0), "=r"(r1), "=r"(r2), "=r"(r3) : "r"(addr))
#define MMA16816(d, a, b) \
    asm volatile("mma.sync.aligned.m16n8k16.row.col.f32.bf16.bf16.f32 " \
                 "{%0,%1,%2,%3}, {%4,%5,%6,%7}, {%8,%9}, {%0,%1,%2,%3};" \
                 : "+f"((d)[0]), "+f"((d)[1]), "+f"((d)[2]), "+f"((d)[3]) \
                 : "r"((a)[0]), "r"((a)[1]), "r"((a)[2]), "r"((a)[3]), \
                   "r"((b)[0]), "r"((b)[1]))

// ---------------------------------------------------------------------------
// Zero sparse output region + pooled accumulator
// ---------------------------------------------------------------------------
__global__ void zero_kernel(float* __restrict__ sparse) {
    const int n4 = (B_ * V_) / 4;
    float4 z = make_float4(0.f, 0.f, 0.f, 0.f);
    float4* p = reinterpret_cast<float4*>(sparse);
    for (int i = blockIdx.x * blockDim.x + threadIdx.x; i < n4;
         i += gridDim.x * blockDim.x)
        p[i] = z;
    // also zero g_pooled (32768 floats = 8192 float4)
    float4* pp = reinterpret_cast<float4*>(g_pooled);
    for (int i = blockIdx.x * blockDim.x + threadIdx.x; i < B_ * H_ / 4;
         i += gridDim.x * blockDim.x)
        pp[i] = z;
}

// ---------------------------------------------------------------------------
// MEGA PASS: one read of hidden does (a) bf16 hi/lo split, (b) masked-pool
// partial accumulation (atomics), (c) per-token sparse dot.
// grid: (B_, S_/32). block: 256 (thread t owns h = 4t..4t+3).
// ---------------------------------------------------------------------------
#define SCH 32
__global__ __launch_bounds__(256, 4)
void mega_pass(const float* __restrict__ x,
               const float* __restrict__ mask,
               const float* __restrict__ sw) {
    const int b = blockIdx.x;
    const int s0 = blockIdx.y * SCH;
    const int tid = threadIdx.x;
    const int wid = tid >> 5, lane = tid & 31;

    __shared__ float msk[SCH];
    __shared__ float red[SCH][8];
    if (tid < SCH) msk[tid] = mask[b * S_ + s0 + tid];
    const float4 w4 = *reinterpret_cast<const float4*>(sw + tid * 4);
    __syncthreads();

    float p0 = 0.f, p1 = 0.f, p2 = 0.f, p3 = 0.f;
    __nv_bfloat162* ahi = reinterpret_cast<__nv_bfloat162*>(g_Ahi);
    __nv_bfloat162* alo = reinterpret_cast<__nv_bfloat162*>(g_Alo);

#pragma unroll 4
    for (int si = 0; si < SCH; si++) {
        const int t = b * S_ + s0 + si;
        const float4 v = *reinterpret_cast<const float4*>(
            x + (size_t)t * H_ + tid * 4);
        // split hi/lo
        __nv_bfloat162 h01 = __floats2bfloat162_rn(v.x, v.y);
        __nv_bfloat162 h23 = __floats2bfloat162_rn(v.z, v.w);
        float2 f01 = __bfloat1622float2(h01);
        float2 f23 = __bfloat1622float2(h23);
        __nv_bfloat162 l01 = __floats2bfloat162_rn(v.x - f01.x, v.y - f01.y);
        __nv_bfloat162 l23 = __floats2bfloat162_rn(v.z - f23.x, v.w - f23.y);
        const size_t o2 = (size_t)t * (H_ / 2) + tid * 2;
        ahi[o2] = h01; ahi[o2 + 1] = h23;
        alo[o2] = l01; alo[o2 + 1] = l23;
        // pooled partials
        const float mk = msk[si];
        p0 += v.x * mk; p1 += v.y * mk; p2 += v.z * mk; p3 += v.w * mk;
        // sparse dot partial -> warp reduce
        float d = v.x * w4.x + v.y * w4.y + v.z * w4.z + v.w * w4.w;
#pragma unroll
        for (int o = 16; o > 0; o >>= 1)
            d += __shfl_down_sync(0xffffffffu, d, o);
        if (lane == 0) red[si][wid] = d;
    }
    __syncthreads();
    // finish tokdot: thread group of 8 per s
    {
        const int si = tid >> 3, j = tid & 7;
        float d = red[si][j];
        d += __shfl_down_sync(0xffffffffu, d, 4);
        d += __shfl_down_sync(0xffffffffu, d, 2);
        d += __shfl_down_sync(0xffffffffu, d, 1);
        if (j == 0) g_tokdot[b * S_ + s0 + si] = d;
    }
    // pooled atomics (16 blocks per b accumulate)
    float* pp = g_pooled + b * H_ + tid * 4;
    atomicAdd(pp + 0, p0);
    atomicAdd(pp + 1, p1);
    atomicAdd(pp + 2, p2);
    atomicAdd(pp + 3, p3);
}

// ---------------------------------------------------------------------------
// masksum[b] = sum_s mask[b,s].  grid: B_, block: 512.
// ---------------------------------------------------------------------------
__global__ void masksum_kernel(const float* __restrict__ mask) {
    const int b = blockIdx.x;
    float v = mask[b * S_ + threadIdx.x];
#pragma unroll
    for (int o = 16; o > 0; o >>= 1)
        v += __shfl_down_sync(0xffffffffu, v, o);
    __shared__ float ws[16];
    if ((threadIdx.x & 31) == 0) ws[threadIdx.x >> 5] = v;
    __syncthreads();
    if (threadIdx.x < 16) {
        float t = ws[threadIdx.x];
#pragma unroll
        for (int o = 8; o > 0; o >>= 1)
            t += __shfl_down_sync(0xffffu, t, o);
        if (threadIdx.x == 0) g_masksum[b] = t;
    }
}

// ---------------------------------------------------------------------------
// Sparse finalize: relu((dot+b)*mask) scatter-add. grid 64, block 256.
// ---------------------------------------------------------------------------
__global__ void sparse_finalize(const float* __restrict__ mask,
                                const float* __restrict__ sb,
                                const int* __restrict__ ids,
                                float* __restrict__ sparse) {
    const int t = blockIdx.x * 256 + threadIdx.x;
    float tw = (g_tokdot[t] + sb[0]) * mask[t];
    if (tw > 0.f) {
        const int b = t / S_;
        const int id = ids[t];
        if (id >= 0 && id < V_)
            atomicAdd(sparse + (size_t)b * V_ + id, tw);
    }
}

// ---------------------------------------------------------------------------
// Split fp32 -> bf16 hi/lo (for mv_w only now)
// ---------------------------------------------------------------------------
__global__ void split_bf16_kernel(const float4* __restrict__ src,
                                  __nv_bfloat162* __restrict__ hi,
                                  __nv_bfloat162* __restrict__ lo, int n4) {
    for (int i = blockIdx.x * blockDim.x + threadIdx.x; i < n4;
         i += gridDim.x * blockDim.x) {
        float4 v = src[i];
        __nv_bfloat162 h01 = __floats2bfloat162_rn(v.x, v.y);
        __nv_bfloat162 h23 = __floats2bfloat162_rn(v.z, v.w);
        float2 f01 = __bfloat1622float2(h01);
        float2 f23 = __bfloat1622float2(h23);
        __nv_bfloat162 l01 = __floats2bfloat162_rn(v.x - f01.x, v.y - f01.y);
        __nv_bfloat162 l23 = __floats2bfloat162_rn(v.z - f23.x, v.w - f23.y);
        hi[i * 2 + 0] = h01;  hi[i * 2 + 1] = h23;
        lo[i * 2 + 0] = l01;  lo[i * 2 + 1] = l23;
    }
}

// ---------------------------------------------------------------------------
// Dense head: block = 8 h-rows x 32 b; weights staged through padded SMEM.
// ---------------------------------------------------------------------------
__global__ __launch_bounds__(256, 4)
void dense_kernel2(const float* __restrict__ dw,
                   const float* __restrict__ db,
                   float* __restrict__ out) {
    __shared__ float ws[8][H_ + 1];
    const int tid = threadIdx.x;
    const int h0 = blockIdx.x * 8;
#pragma unroll
    for (int i = 0; i < 32; i++) {
        int idx = tid + i * 256;
        int r = idx >> 10, c = idx & 1023;
        ws[r][c] = dw[(size_t)(h0 + r) * H_ + c];
    }
    __syncthreads();
    const int b = tid >> 3;
    const int hi = tid & 7;
    const float* p = g_pooled + b * H_;
    float acc = 0.f;
#pragma unroll 8
    for (int k = 0; k < H_; k++) acc += p[k] * ws[hi][k];
    const float pinv = 1.f / g_masksum[b];
    out[b * H_ + h0 + hi] = tanhf(acc * pinv + db[h0 + hi]);
}

// ---------------------------------------------------------------------------
// Row L2-normalize in place (rows of H_=1024)
// ---------------------------------------------------------------------------
__global__ void l2norm_kernel(float* __restrict__ data) {
    float4* row = reinterpret_cast<float4*>(data + (size_t)blockIdx.x * H_);
    float4 v = row[threadIdx.x];
    float ss = v.x * v.x + v.y * v.y + v.z * v.z + v.w * v.w;
#pragma unroll
    for (int o = 16; o > 0; o >>= 1)
        ss += __shfl_down_sync(0xffffffffu, ss, o);
    __shared__ float warp_s[8];
    if ((threadIdx.x & 31) == 0) warp_s[threadIdx.x >> 5] = ss;
    __syncthreads();
    if (threadIdx.x < 8) {
        float t = warp_s[threadIdx.x];
#pragma unroll
        for (int o = 4; o > 0; o >>= 1)
            t += __shfl_down_sync(0xffu, t, o);
        if (threadIdx.x == 0) warp_s[0] = t;
    }
    __syncthreads();
    float scale = 1.f / fmaxf(sqrtf(warp_s[0]), EPS);
    v.x *= scale; v.y *= scale; v.z *= scale; v.w *= scale;
    row[threadIdx.x] = v;
}

// ---------------------------------------------------------------------------
// MV GEMM via mma.sync bf16 (split hi/lo, 3 passes), 3-stage cp.async.
// CTA 128x128, BK=64. 8 warps (2x4), warp tile 64x32.
// Stage (65536 B): Ahi @0, Alo @16384, Whi @32768, Wlo @49152.
// ---------------------------------------------------------------------------
#define NCH 16
#define STG 65536
#define NSTG 3

__device__ __forceinline__ void stage_load(uint32_t smb, int s, int ch,
                                           int m0, int n0, int tid) {
    const int kt = ch * 64;
    const __nv_bfloat16* srcs[4] = {g_Ahi, g_Alo, g_Whi, g_Wlo};
    const int row0s[4] = {m0, m0, n0, n0};
#pragma unroll
    for (int t4 = 0; t4 < 4; t4++) {
        const __nv_bfloat16* src = srcs[t4];
        const int row0 = row0s[t4];
        const uint32_t tb = smb + s * STG + t4 * 16384;
#pragma unroll
        for (int it = 0; it < 4; it++) {
            int q = tid + it * 256;
            int r = q >> 3, c16 = q & 7;
            const void* g = src + (size_t)(row0 + r) * H_ + kt + c16 * 8;
            uint32_t d = tb + (uint32_t)(r * 128 + ((c16 ^ (r & 7)) << 4));
            CP16(d, g);
        }
    }
}

__global__ __launch_bounds__(256, 1)
void mv_gemm_mma(const float* __restrict__ bias,
                 const float* __restrict__ mask,
                 float* __restrict__ C) {
    extern __shared__ char sm[];
    const uint32_t smb = smem_u32(sm);

    const int tid = threadIdx.x;
    const int wid = tid >> 5, lane = tid & 31;
    const int warp_m = wid & 1;
    const int warp_n = wid >> 1;
    const int m0 = blockIdx.y * 128, n0 = blockIdx.x * 128;

    float acc[4][4][4];
#pragma unroll
    for (int i = 0; i < 4; i++)
#pragma unroll
        for (int j = 0; j < 4; j++)
#pragma unroll
            for (int k = 0; k < 4; k++) acc[i][j][k] = 0.f;

    const int g8 = lane >> 3, i8 = lane & 7;
    const int a_r = warp_m * 64 + (g8 & 1) * 8 + i8;
    const int a_cadd = g8 >> 1;
    const int b_r = warp_n * 32 + (g8 >> 1) * 8 + i8;
    const int b_cadd = g8 & 1;

    stage_load(smb, 0, 0, m0, n0, tid);
    CP_COMMIT();
    stage_load(smb, 1, 1, m0, n0, tid);
    CP_COMMIT();

    for (int ch = 0; ch < NCH; ch++) {
        const int s = ch % NSTG;
        if (ch + 2 < NCH) {
            stage_load(smb, (ch + 2) % NSTG, ch + 2, m0, n0, tid);
            CP_COMMIT();
            CP_WAIT2();
        } else if (ch + 1 < NCH) {
            CP_WAIT1();
        } else {
            CP_WAIT0();
        }
        __syncthreads();

        const uint32_t ah = smb + s * STG;
        const uint32_t al = ah + 16384;
        const uint32_t wh = ah + 32768;
        const uint32_t wl = ah + 49152;

#pragma unroll
        for (int ks = 0; ks < 4; ks++) {
            uint32_t Ahi[4][4], Alo[4][4];
#pragma unroll
            for (int mt = 0; mt < 4; mt++) {
                int r = a_r + mt * 16;
                int c16 = ks * 2 + a_cadd;
                uint32_t off = (uint32_t)(r * 128 + ((c16 ^ (r & 7)) << 4));
                LDSM_X4(Ahi[mt][0], Ahi[mt][1], Ahi[mt][2], Ahi[mt][3], ah + off);
                LDSM_X4(Alo[mt][0], Alo[mt][1], Alo[mt][2], Alo[mt][3], al + off);
            }
            uint32_t Bhi[4][2], Blo[4][2];
#pragma unroll
            for (int bh = 0; bh < 2; bh++) {
                int r = b_r + bh * 16;
                int c16 = ks * 2 + b_cadd;
                uint32_t off = (uint32_t)(r * 128 + ((c16 ^ (r & 7)) << 4));
                uint32_t t0, t1, t2, t3;
                LDSM_X4(t0, t1, t2, t3, wh + off);
                Bhi[2 * bh][0] = t0; Bhi[2 * bh][1] = t1;
                Bhi[2 * bh + 1][0] = t2; Bhi[2 * bh + 1][1] = t3;
                LDSM_X4(t0, t1, t2, t3, wl + off);
                Blo[2 * bh][0] = t0; Blo[2 * bh][1] = t1;
                Blo[2 * bh + 1][0] = t2; Blo[2 * bh + 1][1] = t3;
            }
#pragma unroll
            for (int mt = 0; mt < 4; mt++)
#pragma unroll
                for (int ng = 0; ng < 4; ng++) {
                    MMA16816(acc[mt][ng], Ahi[mt], Bhi[ng]);
                    MMA16816(acc[mt][ng], Ahi[mt], Blo[ng]);
                    MMA16816(acc[mt][ng], Alo[mt], Bhi[ng]);
                }
        }
        __syncthreads();
    }

    // epilogue: + bias, * mask, store float2 pairs
#pragma unroll
    for (int mt = 0; mt < 4; mt++) {
        const int r0 = m0 + warp_m * 64 + mt * 16 + (lane >> 2);
        const float mk0 = mask[r0];
        const float mk1 = mask[r0 + 8];
#pragma unroll
        for (int ng = 0; ng < 4; ng++) {
            const int c = n0 + warp_n * 32 + ng * 8 + 2 * (lane & 3);
            const float2 b2 = *reinterpret_cast<const float2*>(bias + c);
            float2 o0, o1;
            o0.x = (acc[mt][ng][0] + b2.x) * mk0;
            o0.y = (acc[mt][ng][1] + b2.y) * mk0;
            o1.x = (acc[mt][ng][2] + b2.x) * mk1;
            o1.y = (acc[mt][ng][3] + b2.y) * mk1;
            *reinterpret_cast<float2*>(C + (size_t)r0 * H_ + c) = o0;
            *reinterpret_cast<float2*>(C + (size_t)(r0 + 8) * H_ + c) = o1;
        }
    }
}

// ---------------------------------------------------------------------------
extern "C" void kernel_launch(void* const* d_in, const int* in_sizes, int n_in,
                              void* d_out, int out_size) {
    const float* hidden   = (const float*)d_in[0];
    const int*   ids      = (const int*)d_in[1];
    const float* attn     = (const float*)d_in[2];
    const float* dense_w  = (const float*)d_in[3];
    const float* dense_b  = (const float*)d_in[4];
    const float* sparse_w = (const float*)d_in[5];
    const float* sparse_b = (const float*)d_in[6];
    const float* mv_w     = (const float*)d_in[7];
    const float* mv_b     = (const float*)d_in[8];

    float* out        = (float*)d_out;
    float* out_dense  = out + OFF_DENSE;
    float* out_sparse = out + OFF_SPARSE;
    float* out_mv     = out + OFF_MV;

    __nv_bfloat16 *whi, *wlo;
    cudaGetSymbolAddress((void**)&whi, g_Whi);
    cudaGetSymbolAddress((void**)&wlo, g_Wlo);

    // 1. zero sparse region + pooled accumulator
    zero_kernel<<<2048, 256>>>(out_sparse);

    // 2. mega pass: split hidden + pooled partials + sparse dots
    {
        dim3 g(B_, S_ / SCH);   // (32, 16)
        mega_pass<<<g, 256>>>(hidden, attn, sparse_w);
    }

    // 3. split W into bf16 hi/lo
    split_bf16_kernel<<<1024, 256>>>((const float4*)mv_w,
                                     (__nv_bfloat162*)whi,
                                     (__nv_bfloat162*)wlo, H_ * H_ / 4);

    // 4. masksum + sparse finalize
    masksum_kernel<<<B_, 512>>>(attn);
    sparse_finalize<<<TOK / 256, 256>>>(attn, sparse_b, ids, out_sparse);

    // 5. dense head + L2 norm
    dense_kernel2<<<H_ / 8, 256>>>(dense_w, dense_b, out_dense);
    l2norm_kernel<<<B_, 256>>>(out_dense);

    // 6. MV GEMM (mma.sync, 3-stage pipeline)
    {
        const int smem_bytes = NSTG * STG;  // 196608
        cudaFuncSetAttribute(mv_gemm_mma,
                             cudaFuncAttributeMaxDynamicSharedMemorySize,
                             smem_bytes);
        dim3 g(H_ / 128, TOK / 128);        // (8, 128)
        mv_gemm_mma<<<g, 256, smem_bytes>>>(mv_b, attn, out_mv);
    }

    // 7. MV per-token L2 norm
    l2norm_kernel<<<TOK, 256>>>(out_mv);
}